// round 8
// baseline (speedup 1.0000x reference)
#include <cuda_runtime.h>
#include <cuda_fp16.h>
#include <mma.h>
#include <cstdint>

using namespace nvcuda;

#define B_   1024
#define H_   512
#define E_   256
#define S_   128
#define T_   128
#define V_   128
#define G4   2048
#define JT_  16
#define NCTA 128
#define NSTEP (S_ + T_ - 1)     // 255
#define THREADS 512
#define LDH  520                // smem ld (halves) for resident W / fc_w rows
#define LDW  72                 // smem ld (halves) for streamed h chunks
#define CHUNKB (128 * LDW * 2)  // 18432 bytes per 64-k chunk
#define WBYTES (128 * LDH * 2)  // 133120: resident W tile
#define GS_B   (128 * 132 * 4)  // 67584: gate-staging fp32 [128 b][132 j]
#define HO_B   (128 * 36 * 4)   // 18432: hout fp32
#define SEQ_SMEM (WBYTES + GS_B + HO_B)               // 219136
#define FC_SMEM  (128 * LDH * 2 + 2 * 128 * LDW * 2)  // 169984

// ---------------- device scratch ----------------
__device__ __half g_W2[2][JT_ * 128 * H_];           // reordered whh fp16: [jt][g*32+h][k]
__device__ float  g_embp[2][(long)V_ * G4];          // emb @ wih^T + bih + bhh (exact fp32)
__device__ __half g_fcw16[V_ * H_];
__device__ float  g_biasfc[16 * V_];
__device__ __half g_hf[2][(long)B_ * H_];            // hidden fp16, double buffered (cross-CTA via L2)
__device__ __half g_hseq[(long)B_ * (T_ - 1) * H_];
__device__ float  g_logits[(long)B_ * (T_ - 1) * V_];
__device__ unsigned g_bar8[8 * 32];                  // per-b-group barrier counters (128B apart)

// fast activations: MUFU-based, rel err ~1e-6 (validated in R7: rel_err unchanged)
__device__ __forceinline__ float sigm(float x) {
    return __fdividef(1.f, 1.f + __expf(-x));
}
__device__ __forceinline__ float tanhfast(float x) {
    float s = __fdividef(1.f, 1.f + __expf(-2.f * x));
    return fmaf(2.f, s, -1.f);
}

__device__ __forceinline__ void cpa16(void* dst, const void* src) {
    unsigned d = (unsigned)__cvta_generic_to_shared(dst);
    asm volatile("cp.async.cg.shared.global [%0], [%1], 16;\n" :: "r"(d), "l"(src));
}
#define CPC()  asm volatile("cp.async.commit_group;\n" ::: "memory")
#define CPW(n) asm volatile("cp.async.wait_group %0;\n" :: "n"(n) : "memory")

// copy 64-k chunk ch of this CTA's h tile into smem buffer (all 512 threads)
#define CPCHUNK(buf, ch)                                                          \
    for (int i_ = threadIdx.x; i_ < 128 * 8; i_ += THREADS) {                     \
        int r_ = i_ >> 3, q_ = i_ & 7;                                            \
        cpa16((buf) + r_ * LDW + q_ * 8, hg + (long)(b0 + r_) * H_ + (ch) * 64 + q_ * 8); \
    }

// ---------------- prep A: embproj = emb @ wih^T + bih + bhh (exact fp32) ----------------
__global__ void prep_embproj(const float* __restrict__ emb, const float* __restrict__ wih,
                             const float* __restrict__ bih, const float* __restrict__ bhh,
                             int is_dec)
{
    __shared__ float er[E_];
    int v = blockIdx.x;
    int n = blockIdx.y * 256 + threadIdx.x;
    er[threadIdx.x] = emb[(long)v * E_ + threadIdx.x];
    __syncthreads();
    float s = bih[n] + bhh[n];
    const float* wr = wih + (long)n * E_;
    #pragma unroll 8
    for (int k = 0; k < E_; k++) s += er[k] * wr[k];
    g_embp[is_dec][(long)v * G4 + n] = s;
}

// ---------------- prep B: reorder whh fp16, fc weights, bias tile, zero h0, reset bars ---
__global__ void prep2(const float* __restrict__ enc_whh, const float* __restrict__ dec_whh,
                      const float* __restrict__ fc_w,    const float* __restrict__ fc_b)
{
    if (blockIdx.x == 0 && threadIdx.x < 8 * 32) g_bar8[threadIdx.x] = 0u;
    const long NW  = (long)JT_ * 128 * H_;
    const long NFC = (long)V_ * H_;
    const long NB  = 16L * V_;
    const long NS  = (long)B_ * H_;
    const long total = 2 * NW + NFC + NB + NS;
    for (long i = (long)blockIdx.x * blockDim.x + threadIdx.x; i < total;
         i += (long)gridDim.x * blockDim.x) {
        long r = i;
        if (r < 2 * NW) {
            int ed = (int)(r / NW);
            long l = r % NW;
            int jt = (int)(l / (128L * H_));
            int rr = (int)((l / H_) % 128);
            int k  = (int)(l % H_);
            int g = rr >> 5, hh = rr & 31;
            long n = (long)g * H_ + jt * 32 + hh;
            const float* whh = ed ? dec_whh : enc_whh;
            g_W2[ed][l] = __float2half(whh[n * H_ + k]);
        } else if (r < 2 * NW + NFC) {
            long l = r - 2 * NW;
            g_fcw16[l] = __float2half(fc_w[l]);
        } else if (r < 2 * NW + NFC + NB) {
            long l = r - 2 * NW - NFC;
            g_biasfc[l] = fc_b[l % V_];
        } else {
            long l = r - 2 * NW - NFC - NB;
            g_hf[0][l] = __float2half(0.f);
        }
    }
}

// ---------------- persistent kernel: all 255 LSTM steps ----------------
// CTA (bt, jt): batch rows bt*128..+127, h-dims jt*32..+31 (x4 gates = 128 gate rows).
// 16 warps: wk = warp>>3 splits K; (wj, wbt) tile 16j x 32b x 2cb.
// Mainloop identical to the R5 best (full-CTA syncs, 512-thread chunk copies).
// Epilogue balanced: each warp cross-stores other-cb partials to GS, finalizes own cb
// (cb = wk) with a single register-resident c fragment. Fast MUFU activations.
__global__ __launch_bounds__(THREADS, 1) void seq_kernel(
    const int* __restrict__ src, const int* __restrict__ tgt)
{
    extern __shared__ __align__(16) char smem[];
    __half* Ws = (__half*)smem;                       // [128 gate-row][LDH k] resident
    __half* hb[4];
    #pragma unroll
    for (int i = 0; i < 4; i++) hb[i] = (__half*)(smem + WBYTES + i * CHUNKB);
    float* GS   = (float*)(smem + WBYTES);            // [128 b][132 j] gate staging (aliases hb)
    float* hout = (float*)(smem + WBYTES + GS_B);     // [128 b][36 h]
    __shared__ int tok_s[128];

    const int tid  = threadIdx.x;
    const int warp = tid >> 5;
    const int wk   = warp >> 3;         // K half (also: owned cb in epilogue)
    const int wj   = warp & 1;          // j sub-tile (16)
    const int wbt  = (warp >> 1) & 3;   // batch sub-tile (32)
    const int jt   = blockIdx.x & 15;
    const int b0   = (blockIdx.x >> 4) * 128;
    const int btg  = blockIdx.x >> 4;   // barrier group

    // resident encoder W tile
    {
        const __half* __restrict__ W = g_W2[0] + (long)jt * 128 * H_;
        for (int i = tid; i < 128 * 64; i += THREADS) {
            int r = i >> 6, q = i & 63;
            cpa16(Ws + r * LDH + q * 8, W + (long)r * H_ + q * 8);
        }
        CPC(); CPW(0);
        __syncthreads();
    }

    // persistent cell state: this warp owns cb = wk for its (wbt, wj) tile
    wmma::fragment<wmma::accumulator, 16, 16, 16, float> cfr;
    wmma::fill_fragment(cfr, 0.f);

    for (int st = 0; st < NSTEP; ++st) {
        const int is_dec = st >= S_;
        const int t   = is_dec ? st - S_ : st;
        const int par = st & 1;
        const int* __restrict__ tok = is_dec ? tgt : src;
        const __half* __restrict__ hg = g_hf[par];

        if (st == S_) {   // swap to decoder weights (CTA-local)
            const __half* __restrict__ W = g_W2[1] + (long)jt * 128 * H_;
            for (int i = tid; i < 128 * 64; i += THREADS) {
                int r = i >> 6, q = i & 63;
                cpa16(Ws + r * LDH + q * 8, W + (long)r * H_ + q * 8);
            }
            CPC(); CPW(0);
            __syncthreads();
        }

        if (tid < 128) tok_s[tid] = tok[(long)(b0 + tid) * 128 + t];

        // prologue: pair0 = chunks {0,4}, pair1 = {1,5}
        CPCHUNK(hb[0], 0); CPCHUNK(hb[2], 4); CPC();
        CPCHUNK(hb[1], 1); CPCHUNK(hb[3], 5); CPC();

        wmma::fragment<wmma::accumulator, 16, 16, 16, float> acc[4][2];
        #pragma unroll
        for (int g = 0; g < 4; g++) {
            wmma::fill_fragment(acc[g][0], 0.f);
            wmma::fill_fragment(acc[g][1], 0.f);
        }

        #pragma unroll 1
        for (int c = 0; c < 4; c++) {
            if (c < 3) { CPW(1); } else { CPW(0); }
            __syncthreads();
            const __half* cw = hb[2 * wk + (c & 1)];
            const int ch = wk * 4 + c;           // this warp's K chunk
            #pragma unroll
            for (int kk = 0; kk < 4; kk++) {
                wmma::fragment<wmma::matrix_b, 16, 16, 16, half, wmma::col_major> bf[2];
                #pragma unroll
                for (int cb = 0; cb < 2; cb++)
                    wmma::load_matrix_sync(bf[cb], cw + (wbt * 32 + cb * 16) * LDW + kk * 16, LDW);
                #pragma unroll
                for (int g = 0; g < 4; g++) {
                    wmma::fragment<wmma::matrix_a, 16, 16, 16, half, wmma::row_major> af;
                    wmma::load_matrix_sync(af, Ws + (g * 32 + wj * 16) * LDH + ch * 64 + kk * 16, LDH);
                    wmma::mma_sync(acc[g][0], af, bf[0], acc[g][0]);
                    wmma::mma_sync(acc[g][1], af, bf[1], acc[g][1]);
                }
            }
            __syncthreads();
            if (c + 2 < 4) {
                CPCHUNK(hb[c & 1], c + 2);
                CPCHUNK(hb[2 + (c & 1)], 4 + c + 2);
                CPC();
            }
        }

        // -------- epilogue (balanced) --------
        // cross-store: each warp dumps its OTHER-cb partials into GS
        {
            const int ocb = wk ^ 1;
            #pragma unroll
            for (int g = 0; g < 4; g++)
                wmma::store_matrix_sync(GS + (wbt * 32 + ocb * 16) * 132 + g * 32 + wj * 16,
                                        acc[g][ocb], 132, wmma::mem_col_major);
        }
        __syncthreads();

        // all threads: GS += embproj gather (vectorized)
        const float* __restrict__ EP = g_embp[is_dec];
        for (int i = tid; i < 128 * 32; i += THREADS) {
            int b = i >> 5, j4 = (i & 31) * 4;
            int g = j4 >> 5, hh = j4 & 31;
            const float4 ev = *reinterpret_cast<const float4*>(
                &EP[(long)tok_s[b] * G4 + (long)g * H_ + jt * 32 + hh]);
            float4* gp = reinterpret_cast<float4*>(&GS[b * 132 + j4]);
            float4 gv = *gp;
            gv.x += ev.x; gv.y += ev.y; gv.z += ev.z; gv.w += ev.w;
            *gp = gv;
        }
        __syncthreads();

        // own-cb finalize: combine + cell update (c in registers), stage h
        {
            const int mycb = wk;
            const int bl = wbt * 32 + mycb * 16;
            wmma::fragment<wmma::accumulator, 16, 16, 16, float> xf, hn;
            #pragma unroll
            for (int g = 0; g < 4; g++) {
                wmma::load_matrix_sync(xf, GS + bl * 132 + g * 32 + wj * 16, 132, wmma::mem_col_major);
                #pragma unroll
                for (int e = 0; e < 8; e++) acc[g][mycb].x[e] += xf.x[e];
            }
            #pragma unroll
            for (int e = 0; e < 8; e++) {
                float ig = sigm(acc[0][mycb].x[e]);
                float fg = sigm(acc[1][mycb].x[e]);
                float gg = tanhfast(acc[2][mycb].x[e]);
                float og = sigm(acc[3][mycb].x[e]);
                float c2 = fg * cfr.x[e] + ig * gg;
                cfr.x[e] = c2;
                hn.x[e] = og * tanhfast(c2);
            }
            wmma::store_matrix_sync(hout + bl * 36 + wj * 16, hn, 36, wmma::mem_col_major);
        }
        __syncthreads();

        // all threads: write h (fp16) to global (+ hseq if decoder)
        __half* __restrict__ hg2 = g_hf[par ^ 1];
        for (int i = tid; i < 128 * 32; i += THREADS) {
            int b = i >> 5, hh = i & 31;
            __half v = __float2half(hout[b * 36 + hh]);
            hg2[(long)(b0 + b) * H_ + jt * 32 + hh] = v;
            if (is_dec)
                g_hseq[((long)(b0 + b) * (T_ - 1) + t) * H_ + jt * 32 + hh] = v;
        }

        // -------- per-b-group barrier (16 CTAs), tid0-only fence --------
        if (st + 1 < NSTEP) {
            __syncthreads();
            if (tid == 0) {
                __threadfence();                   // cumulative after syncthreads (CG pattern)
                atomicAdd(&g_bar8[btg * 32], 1u);
                const unsigned target = (unsigned)(st + 1) * 16u;
                while (*(volatile unsigned*)&g_bar8[btg * 32] < target) __nanosleep(64);
            }
            __syncthreads();
        }
    }
}

// ---------------- FC head: logits = h_seq @ fc_w^T + fc_b (fp16 in, fp32 acc) ----------
__global__ __launch_bounds__(256, 1) void fc_kernel()
{
    extern __shared__ __align__(16) char smem[];
    __half* bsm = (__half*)smem;
    __half* ab0 = (__half*)(smem + 128 * LDH * 2);
    __half* ab1 = (__half*)(smem + 128 * LDH * 2 + 128 * LDW * 2);

    const int tid = threadIdx.x;
    const int warp = tid >> 5;
    const int wm = warp >> 2;
    const int wn = warp & 3;
    const long m0 = (long)blockIdx.x * 128;

    for (int i = tid; i < 128 * 64; i += 256) {
        int r = i >> 6, q = i & 63;
        cpa16(bsm + r * LDH + q * 8, g_fcw16 + (long)r * H_ + q * 8);
    }
    for (int i = tid; i < 128 * 8; i += 256) {
        int r = i >> 3, q = i & 7;
        cpa16(ab0 + r * LDW + q * 8, g_hseq + (m0 + r) * H_ + q * 8);
    }
    CPC();
    for (int i = tid; i < 128 * 8; i += 256) {
        int r = i >> 3, q = i & 7;
        cpa16(ab1 + r * LDW + q * 8, g_hseq + (m0 + r) * H_ + 64 + q * 8);
    }
    CPC();
    CPW(1);
    __syncthreads();

    wmma::fragment<wmma::accumulator, 16, 16, 16, float> acc[4][2];
    #pragma unroll
    for (int mm = 0; mm < 4; mm++)
        #pragma unroll
        for (int cb = 0; cb < 2; cb++)
            wmma::load_matrix_sync(acc[mm][cb], g_biasfc + wn * 32 + cb * 16, V_, wmma::mem_row_major);

    #pragma unroll 1
    for (int ch = 0; ch < 8; ch++) {
        const __half* ca = (ch & 1) ? ab1 : ab0;
        #pragma unroll
        for (int kk = 0; kk < 4; kk++) {
            wmma::fragment<wmma::matrix_b, 16, 16, 16, half, wmma::col_major> bf[2];
            #pragma unroll
            for (int cb = 0; cb < 2; cb++)
                wmma::load_matrix_sync(bf[cb], bsm + (wn * 32 + cb * 16) * LDH + ch * 64 + kk * 16, LDH);
            #pragma unroll
            for (int mm = 0; mm < 4; mm++) {
                wmma::fragment<wmma::matrix_a, 16, 16, 16, half, wmma::row_major> af;
                wmma::load_matrix_sync(af, ca + (wm * 64 + mm * 16) * LDW + kk * 16, LDW);
                wmma::mma_sync(acc[mm][0], af, bf[0], acc[mm][0]);
                wmma::mma_sync(acc[mm][1], af, bf[1], acc[mm][1]);
            }
        }
        __syncthreads();
        if (ch + 2 < 8) {
            __half* nb = (ch & 1) ? ab1 : ab0;
            for (int i = tid; i < 128 * 8; i += 256) {
                int r = i >> 3, q = i & 7;
                cpa16(nb + r * LDW + q * 8, g_hseq + (m0 + r) * H_ + (ch + 2) * 64 + q * 8);
            }
            CPC();
        }
        if (ch + 1 < 8) {
            if (ch + 2 < 8) { CPW(1); } else { CPW(0); }
            __syncthreads();
        }
    }

    #pragma unroll
    for (int mm = 0; mm < 4; mm++)
        #pragma unroll
        for (int cb = 0; cb < 2; cb++)
            wmma::store_matrix_sync(g_logits + (m0 + wm * 64 + mm * 16) * V_ + wn * 32 + cb * 16,
                                    acc[mm][cb], V_, wmma::mem_row_major);
}

// ---------------- scatter logits into (B, T, V) with zero row at t=0 ----------------
__global__ void out_kernel(float* __restrict__ out)
{
    const long n4 = (long)B_ * T_ * V_ / 4;
    for (long i = (long)blockIdx.x * blockDim.x + threadIdx.x; i < n4;
         i += (long)gridDim.x * blockDim.x) {
        long e = i * 4;
        int  v  = (int)(e % V_);
        long bt = e / V_;
        int  tt = (int)(bt % T_);
        long b  = bt / T_;
        float4 val;
        if (tt == 0) val = make_float4(0.f, 0.f, 0.f, 0.f);
        else val = *reinterpret_cast<const float4*>(
                       &g_logits[(b * (T_ - 1) + (tt - 1)) * V_ + v]);
        reinterpret_cast<float4*>(out)[i] = val;
    }
}

// ---------------- launch ----------------
extern "C" void kernel_launch(void* const* d_in, const int* in_sizes, int n_in,
                              void* d_out, int out_size)
{
    (void)in_sizes; (void)n_in; (void)out_size;
    const int*   src      = (const int*)  d_in[0];
    const int*   target   = (const int*)  d_in[1];
    const float* emb      = (const float*)d_in[2];
    const float* dec_emb  = (const float*)d_in[3];
    const float* enc_wih  = (const float*)d_in[4];
    const float* enc_whh  = (const float*)d_in[5];
    const float* enc_bih  = (const float*)d_in[6];
    const float* enc_bhh  = (const float*)d_in[7];
    const float* dec_wih  = (const float*)d_in[8];
    const float* dec_whh  = (const float*)d_in[9];
    const float* dec_bih  = (const float*)d_in[10];
    const float* dec_bhh  = (const float*)d_in[11];
    const float* fc_w     = (const float*)d_in[12];
    const float* fc_b     = (const float*)d_in[13];
    float* out = (float*)d_out;

    cudaFuncSetAttribute(seq_kernel, cudaFuncAttributeMaxDynamicSharedMemorySize, SEQ_SMEM);
    cudaFuncSetAttribute(fc_kernel,  cudaFuncAttributeMaxDynamicSharedMemorySize, FC_SMEM);

    prep_embproj<<<dim3(V_, G4 / 256), 256>>>(emb,     enc_wih, enc_bih, enc_bhh, 0);
    prep_embproj<<<dim3(V_, G4 / 256), 256>>>(dec_emb, dec_wih, dec_bih, dec_bhh, 1);
    prep2<<<2048, 256>>>(enc_whh, dec_whh, fc_w, fc_b);

    seq_kernel<<<NCTA, THREADS, SEQ_SMEM>>>(src, target);

    fc_kernel<<<(B_ * (T_ - 1)) / 128, 256, FC_SMEM>>>();
    out_kernel<<<2048, 256>>>(out);
}

// round 9
// speedup vs baseline: 1.2151x; 1.2151x over previous
#include <cuda_runtime.h>
#include <cuda_fp16.h>
#include <mma.h>
#include <cstdint>

using namespace nvcuda;

#define B_   1024
#define H_   512
#define E_   256
#define S_   128
#define T_   128
#define V_   128
#define G4   2048
#define JT_  16
#define NCTA 128
#define NSTEP (S_ + T_ - 1)     // 255
#define THREADS 512
#define LDH  520                // smem ld (halves) for resident W / fc_w rows
#define LDW  72                 // smem ld (halves) for streamed h chunks
#define CHUNKB (128 * LDW * 2)  // 18432 bytes per 64-k chunk
#define WBYTES (128 * LDH * 2)  // 133120: resident W tile
#define GS_B   (128 * 132 * 4)  // 67584: gate-staging fp32 [128 b][132 j]
#define HO_B   (128 * 36 * 4)   // 18432: hout fp32
#define SEQ_SMEM (WBYTES + GS_B + HO_B)               // 219136
#define FC_SMEM  (128 * LDH * 2 + 2 * 128 * LDW * 2)  // 169984

// ---------------- device scratch ----------------
__device__ __half g_W2[2][JT_ * 128 * H_];           // reordered whh fp16: [jt][g*32+h][k]
__device__ float  g_embp[2][(long)V_ * G4];          // emb @ wih^T + bih + bhh (exact fp32)
__device__ __half g_fcw16[V_ * H_];
__device__ float  g_biasfc[16 * V_];
__device__ __half g_hf[2][(long)B_ * H_];            // hidden fp16, double buffered (cross-CTA via L2)
__device__ __half g_hseq[(long)B_ * (T_ - 1) * H_];
__device__ float  g_logits[(long)B_ * (T_ - 1) * V_];
__device__ unsigned g_bar8[8 * 32];                  // per-b-group barrier counters (128B apart)

// fast activations: MUFU-based, rel err ~1e-6 (numerically validated in R7/R8)
__device__ __forceinline__ float sigm(float x) {
    return __fdividef(1.f, 1.f + __expf(-x));
}
__device__ __forceinline__ float tanhfast(float x) {
    float s = __fdividef(1.f, 1.f + __expf(-2.f * x));
    return fmaf(2.f, s, -1.f);
}

__device__ __forceinline__ void cpa16(void* dst, const void* src) {
    unsigned d = (unsigned)__cvta_generic_to_shared(dst);
    asm volatile("cp.async.cg.shared.global [%0], [%1], 16;\n" :: "r"(d), "l"(src));
}
#define CPC()  asm volatile("cp.async.commit_group;\n" ::: "memory")
#define CPW(n) asm volatile("cp.async.wait_group %0;\n" :: "n"(n) : "memory")

// copy 64-k chunk ch of this CTA's h tile into smem buffer (all 512 threads)
#define CPCHUNK(buf, ch)                                                          \
    for (int i_ = threadIdx.x; i_ < 128 * 8; i_ += THREADS) {                     \
        int r_ = i_ >> 3, q_ = i_ & 7;                                            \
        cpa16((buf) + r_ * LDW + q_ * 8, hg + (long)(b0 + r_) * H_ + (ch) * 64 + q_ * 8); \
    }

// ---------------- prep A: embproj = emb @ wih^T + bih + bhh (exact fp32) ----------------
__global__ void prep_embproj(const float* __restrict__ emb, const float* __restrict__ wih,
                             const float* __restrict__ bih, const float* __restrict__ bhh,
                             int is_dec)
{
    __shared__ float er[E_];
    int v = blockIdx.x;
    int n = blockIdx.y * 256 + threadIdx.x;
    er[threadIdx.x] = emb[(long)v * E_ + threadIdx.x];
    __syncthreads();
    float s = bih[n] + bhh[n];
    const float* wr = wih + (long)n * E_;
    #pragma unroll 8
    for (int k = 0; k < E_; k++) s += er[k] * wr[k];
    g_embp[is_dec][(long)v * G4 + n] = s;
}

// ---------------- prep B: reorder whh fp16, fc weights, bias tile, zero h0, reset bars ---
__global__ void prep2(const float* __restrict__ enc_whh, const float* __restrict__ dec_whh,
                      const float* __restrict__ fc_w,    const float* __restrict__ fc_b)
{
    if (blockIdx.x == 0 && threadIdx.x < 8 * 32) g_bar8[threadIdx.x] = 0u;
    const long NW  = (long)JT_ * 128 * H_;
    const long NFC = (long)V_ * H_;
    const long NB  = 16L * V_;
    const long NS  = (long)B_ * H_;
    const long total = 2 * NW + NFC + NB + NS;
    for (long i = (long)blockIdx.x * blockDim.x + threadIdx.x; i < total;
         i += (long)gridDim.x * blockDim.x) {
        long r = i;
        if (r < 2 * NW) {
            int ed = (int)(r / NW);
            long l = r % NW;
            int jt = (int)(l / (128L * H_));
            int rr = (int)((l / H_) % 128);
            int k  = (int)(l % H_);
            int g = rr >> 5, hh = rr & 31;
            long n = (long)g * H_ + jt * 32 + hh;
            const float* whh = ed ? dec_whh : enc_whh;
            g_W2[ed][l] = __float2half(whh[n * H_ + k]);
        } else if (r < 2 * NW + NFC) {
            long l = r - 2 * NW;
            g_fcw16[l] = __float2half(fc_w[l]);
        } else if (r < 2 * NW + NFC + NB) {
            long l = r - 2 * NW - NFC;
            g_biasfc[l] = fc_b[l % V_];
        } else {
            long l = r - 2 * NW - NFC - NB;
            g_hf[0][l] = __float2half(0.f);
        }
    }
}

// ---------------- persistent kernel: all 255 LSTM steps (R5 structure, fast activations) --
// CTA (bt, jt): batch rows bt*128..+127, h-dims jt*32..+31 (x4 gates = 128 gate rows).
// 16 warps: wk = warp>>3 splits K; (wj, wbt) tile 16j x 32b x 2cb. c state in wk=0 regs.
// Cross-CTA h via L2 (STG -> all-thread fence -> per-b-group 16-CTA barrier -> cp.async.cg).
__global__ __launch_bounds__(THREADS, 1) void seq_kernel(
    const int* __restrict__ src, const int* __restrict__ tgt)
{
    extern __shared__ __align__(16) char smem[];
    __half* Ws = (__half*)smem;                       // [128 gate-row][LDH k] resident
    __half* hb[4];
    #pragma unroll
    for (int i = 0; i < 4; i++) hb[i] = (__half*)(smem + WBYTES + i * CHUNKB);
    float* GS   = (float*)(smem + WBYTES);            // [128 b][132 j] gate staging (aliases hb)
    float* hout = (float*)(smem + WBYTES + GS_B);     // [128 b][36 h]
    __shared__ int tok_s[128];

    const int tid  = threadIdx.x;
    const int warp = tid >> 5;
    const int wk   = warp >> 3;         // K half
    const int wj   = warp & 1;          // j sub-tile (16)
    const int wbt  = (warp >> 1) & 3;   // batch sub-tile (32)
    const int jt   = blockIdx.x & 15;
    const int b0   = (blockIdx.x >> 4) * 128;
    const int btg  = blockIdx.x >> 4;   // barrier group

    // resident encoder W tile
    {
        const __half* __restrict__ W = g_W2[0] + (long)jt * 128 * H_;
        for (int i = tid; i < 128 * 64; i += THREADS) {
            int r = i >> 6, q = i & 63;
            cpa16(Ws + r * LDH + q * 8, W + (long)r * H_ + q * 8);
        }
        CPC(); CPW(0);
        __syncthreads();
    }

    // persistent cell state (wk=0 warps only)
    wmma::fragment<wmma::accumulator, 16, 16, 16, float> cfr[2];
    wmma::fill_fragment(cfr[0], 0.f);
    wmma::fill_fragment(cfr[1], 0.f);

    for (int st = 0; st < NSTEP; ++st) {
        const int is_dec = st >= S_;
        const int t   = is_dec ? st - S_ : st;
        const int par = st & 1;
        const int* __restrict__ tok = is_dec ? tgt : src;
        const __half* __restrict__ hg = g_hf[par];

        if (st == S_) {   // swap to decoder weights (CTA-local)
            const __half* __restrict__ W = g_W2[1] + (long)jt * 128 * H_;
            for (int i = tid; i < 128 * 64; i += THREADS) {
                int r = i >> 6, q = i & 63;
                cpa16(Ws + r * LDH + q * 8, W + (long)r * H_ + q * 8);
            }
            CPC(); CPW(0);
            __syncthreads();
        }

        if (tid < 128) tok_s[tid] = tok[(long)(b0 + tid) * 128 + t];

        // prologue: pair0 = chunks {0,4}, pair1 = {1,5}
        CPCHUNK(hb[0], 0); CPCHUNK(hb[2], 4); CPC();
        CPCHUNK(hb[1], 1); CPCHUNK(hb[3], 5); CPC();

        wmma::fragment<wmma::accumulator, 16, 16, 16, float> acc[4][2];
        #pragma unroll
        for (int g = 0; g < 4; g++) {
            wmma::fill_fragment(acc[g][0], 0.f);
            wmma::fill_fragment(acc[g][1], 0.f);
        }

        #pragma unroll 1
        for (int c = 0; c < 4; c++) {
            if (c < 3) { CPW(1); } else { CPW(0); }
            __syncthreads();
            const __half* cw = hb[2 * wk + (c & 1)];
            const int ch = wk * 4 + c;           // this warp's K chunk
            #pragma unroll
            for (int kk = 0; kk < 4; kk++) {
                wmma::fragment<wmma::matrix_b, 16, 16, 16, half, wmma::col_major> bf[2];
                #pragma unroll
                for (int cb = 0; cb < 2; cb++)
                    wmma::load_matrix_sync(bf[cb], cw + (wbt * 32 + cb * 16) * LDW + kk * 16, LDW);
                #pragma unroll
                for (int g = 0; g < 4; g++) {
                    wmma::fragment<wmma::matrix_a, 16, 16, 16, half, wmma::row_major> af;
                    wmma::load_matrix_sync(af, Ws + (g * 32 + wj * 16) * LDH + ch * 64 + kk * 16, LDH);
                    wmma::mma_sync(acc[g][0], af, bf[0], acc[g][0]);
                    wmma::mma_sync(acc[g][1], af, bf[1], acc[g][1]);
                }
            }
            __syncthreads();
            if (c + 2 < 4) {
                CPCHUNK(hb[c & 1], c + 2);
                CPCHUNK(hb[2 + (c & 1)], 4 + c + 2);
                CPC();
            }
        }

        // -------- epilogue (R5 structure: wk=1 stores, wk=0 finalizes) --------
        if (wk == 1) {
            #pragma unroll
            for (int g = 0; g < 4; g++)
                #pragma unroll
                for (int cb = 0; cb < 2; cb++)
                    wmma::store_matrix_sync(GS + (wbt * 32 + cb * 16) * 132 + g * 32 + wj * 16,
                                            acc[g][cb], 132, wmma::mem_col_major);
        }
        __syncthreads();

        // all threads: GS += embproj gather (vectorized)
        const float* __restrict__ EP = g_embp[is_dec];
        for (int i = tid; i < 128 * 32; i += THREADS) {
            int b = i >> 5, j4 = (i & 31) * 4;
            int g = j4 >> 5, hh = j4 & 31;
            const float4 ev = *reinterpret_cast<const float4*>(
                &EP[(long)tok_s[b] * G4 + (long)g * H_ + jt * 32 + hh]);
            float4* gp = reinterpret_cast<float4*>(&GS[b * 132 + j4]);
            float4 gv = *gp;
            gv.x += ev.x; gv.y += ev.y; gv.z += ev.z; gv.w += ev.w;
            *gp = gv;
        }
        __syncthreads();

        // wk=0 warps: combine + cell update (c in registers), stage h
        if (wk == 0) {
            #pragma unroll
            for (int cb = 0; cb < 2; cb++) {
                const int bl = wbt * 32 + cb * 16;
                wmma::fragment<wmma::accumulator, 16, 16, 16, float> xf, hn;
                #pragma unroll
                for (int g = 0; g < 4; g++) {
                    wmma::load_matrix_sync(xf, GS + bl * 132 + g * 32 + wj * 16, 132, wmma::mem_col_major);
                    #pragma unroll
                    for (int e = 0; e < 8; e++) acc[g][cb].x[e] += xf.x[e];
                }
                #pragma unroll
                for (int e = 0; e < 8; e++) {
                    float ig = sigm(acc[0][cb].x[e]);
                    float fg = sigm(acc[1][cb].x[e]);
                    float gg = tanhfast(acc[2][cb].x[e]);
                    float og = sigm(acc[3][cb].x[e]);
                    float c2 = fg * cfr[cb].x[e] + ig * gg;
                    cfr[cb].x[e] = c2;
                    hn.x[e] = og * tanhfast(c2);
                }
                wmma::store_matrix_sync(hout + bl * 36 + wj * 16, hn, 36, wmma::mem_col_major);
            }
        }
        __syncthreads();

        // all threads: write h (fp16) to global (+ hseq if decoder)
        __half* __restrict__ hg2 = g_hf[par ^ 1];
        for (int i = tid; i < 128 * 32; i += THREADS) {
            int b = i >> 5, hh = i & 31;
            __half v = __float2half(hout[b * 36 + hh]);
            hg2[(long)(b0 + b) * H_ + jt * 32 + hh] = v;
            if (is_dec)
                g_hseq[((long)(b0 + b) * (T_ - 1) + t) * H_ + jt * 32 + hh] = v;
        }

        // -------- per-b-group barrier (16 CTAs) --------
        if (st + 1 < NSTEP) {
            __threadfence();                      // release h writes (all threads)
            __syncthreads();
            if (tid == 0) {
                atomicAdd(&g_bar8[btg * 32], 1u);
                const unsigned target = (unsigned)(st + 1) * 16u;
                while (*(volatile unsigned*)&g_bar8[btg * 32] < target) __nanosleep(64);
            }
            __syncthreads();
        }
    }
}

// ---------------- FC head: logits = h_seq @ fc_w^T + fc_b (fp16 in, fp32 acc) ----------
__global__ __launch_bounds__(256, 1) void fc_kernel()
{
    extern __shared__ __align__(16) char smem[];
    __half* bsm = (__half*)smem;
    __half* ab0 = (__half*)(smem + 128 * LDH * 2);
    __half* ab1 = (__half*)(smem + 128 * LDH * 2 + 128 * LDW * 2);

    const int tid = threadIdx.x;
    const int warp = tid >> 5;
    const int wm = warp >> 2;
    const int wn = warp & 3;
    const long m0 = (long)blockIdx.x * 128;

    for (int i = tid; i < 128 * 64; i += 256) {
        int r = i >> 6, q = i & 63;
        cpa16(bsm + r * LDH + q * 8, g_fcw16 + (long)r * H_ + q * 8);
    }
    for (int i = tid; i < 128 * 8; i += 256) {
        int r = i >> 3, q = i & 7;
        cpa16(ab0 + r * LDW + q * 8, g_hseq + (m0 + r) * H_ + q * 8);
    }
    CPC();
    for (int i = tid; i < 128 * 8; i += 256) {
        int r = i >> 3, q = i & 7;
        cpa16(ab1 + r * LDW + q * 8, g_hseq + (m0 + r) * H_ + 64 + q * 8);
    }
    CPC();
    CPW(1);
    __syncthreads();

    wmma::fragment<wmma::accumulator, 16, 16, 16, float> acc[4][2];
    #pragma unroll
    for (int mm = 0; mm < 4; mm++)
        #pragma unroll
        for (int cb = 0; cb < 2; cb++)
            wmma::load_matrix_sync(acc[mm][cb], g_biasfc + wn * 32 + cb * 16, V_, wmma::mem_row_major);

    #pragma unroll 1
    for (int ch = 0; ch < 8; ch++) {
        const __half* ca = (ch & 1) ? ab1 : ab0;
        #pragma unroll
        for (int kk = 0; kk < 4; kk++) {
            wmma::fragment<wmma::matrix_b, 16, 16, 16, half, wmma::col_major> bf[2];
            #pragma unroll
            for (int cb = 0; cb < 2; cb++)
                wmma::load_matrix_sync(bf[cb], bsm + (wn * 32 + cb * 16) * LDH + ch * 64 + kk * 16, LDH);
            #pragma unroll
            for (int mm = 0; mm < 4; mm++) {
                wmma::fragment<wmma::matrix_a, 16, 16, 16, half, wmma::row_major> af;
                wmma::load_matrix_sync(af, ca + (wm * 64 + mm * 16) * LDW + kk * 16, LDW);
                wmma::mma_sync(acc[mm][0], af, bf[0], acc[mm][0]);
                wmma::mma_sync(acc[mm][1], af, bf[1], acc[mm][1]);
            }
        }
        __syncthreads();
        if (ch + 2 < 8) {
            __half* nb = (ch & 1) ? ab1 : ab0;
            for (int i = tid; i < 128 * 8; i += 256) {
                int r = i >> 3, q = i & 7;
                cpa16(nb + r * LDW + q * 8, g_hseq + (m0 + r) * H_ + (ch + 2) * 64 + q * 8);
            }
            CPC();
        }
        if (ch + 1 < 8) {
            if (ch + 2 < 8) { CPW(1); } else { CPW(0); }
            __syncthreads();
        }
    }

    #pragma unroll
    for (int mm = 0; mm < 4; mm++)
        #pragma unroll
        for (int cb = 0; cb < 2; cb++)
            wmma::store_matrix_sync(g_logits + (m0 + wm * 64 + mm * 16) * V_ + wn * 32 + cb * 16,
                                    acc[mm][cb], V_, wmma::mem_row_major);
}

// ---------------- scatter logits into (B, T, V) with zero row at t=0 ----------------
__global__ void out_kernel(float* __restrict__ out)
{
    const long n4 = (long)B_ * T_ * V_ / 4;
    for (long i = (long)blockIdx.x * blockDim.x + threadIdx.x; i < n4;
         i += (long)gridDim.x * blockDim.x) {
        long e = i * 4;
        int  v  = (int)(e % V_);
        long bt = e / V_;
        int  tt = (int)(bt % T_);
        long b  = bt / T_;
        float4 val;
        if (tt == 0) val = make_float4(0.f, 0.f, 0.f, 0.f);
        else val = *reinterpret_cast<const float4*>(
                       &g_logits[(b * (T_ - 1) + (tt - 1)) * V_ + v]);
        reinterpret_cast<float4*>(out)[i] = val;
    }
}

// ---------------- launch ----------------
extern "C" void kernel_launch(void* const* d_in, const int* in_sizes, int n_in,
                              void* d_out, int out_size)
{
    (void)in_sizes; (void)n_in; (void)out_size;
    const int*   src      = (const int*)  d_in[0];
    const int*   target   = (const int*)  d_in[1];
    const float* emb      = (const float*)d_in[2];
    const float* dec_emb  = (const float*)d_in[3];
    const float* enc_wih  = (const float*)d_in[4];
    const float* enc_whh  = (const float*)d_in[5];
    const float* enc_bih  = (const float*)d_in[6];
    const float* enc_bhh  = (const float*)d_in[7];
    const float* dec_wih  = (const float*)d_in[8];
    const float* dec_whh  = (const float*)d_in[9];
    const float* dec_bih  = (const float*)d_in[10];
    const float* dec_bhh  = (const float*)d_in[11];
    const float* fc_w     = (const float*)d_in[12];
    const float* fc_b     = (const float*)d_in[13];
    float* out = (float*)d_out;

    cudaFuncSetAttribute(seq_kernel, cudaFuncAttributeMaxDynamicSharedMemorySize, SEQ_SMEM);
    cudaFuncSetAttribute(fc_kernel,  cudaFuncAttributeMaxDynamicSharedMemorySize, FC_SMEM);

    prep_embproj<<<dim3(V_, G4 / 256), 256>>>(emb,     enc_wih, enc_bih, enc_bhh, 0);
    prep_embproj<<<dim3(V_, G4 / 256), 256>>>(dec_emb, dec_wih, dec_bih, dec_bhh, 1);
    prep2<<<2048, 256>>>(enc_whh, dec_whh, fc_w, fc_b);

    seq_kernel<<<NCTA, THREADS, SEQ_SMEM>>>(src, target);

    fc_kernel<<<(B_ * (T_ - 1)) / 128, 256, FC_SMEM>>>();
    out_kernel<<<2048, 256>>>(out);
}

// round 12
// speedup vs baseline: 1.9217x; 1.5815x over previous
#include <cuda_runtime.h>
#include <cuda_fp16.h>
#include <mma.h>
#include <cstdint>

using namespace nvcuda;

#define B_   1024
#define H_   512
#define E_   256
#define S_   128
#define T_   128
#define V_   128
#define G4   2048
#define JT_  16
#define NCTA 128
#define NSTEP (S_ + T_ - 1)     // 255
#define THREADS 512
#define LDH  520                // smem ld (halves) for resident W / fc_w rows
#define LDW  72                 // smem ld (halves) for streamed h chunks
#define CHUNKB (128 * LDW * 2)  // 18432 bytes per 64-k chunk
#define WBYTES (128 * LDH * 2)  // 133120: resident W tile
#define GS_B   (128 * 132 * 4)  // 67584: gate-staging fp32 [128 b][132 j]
#define HO_B   (128 * 36 * 4)   // 18432: hout fp32
#define SEQ_SMEM (WBYTES + GS_B + HO_B)               // 219136
#define FC_SMEM  (128 * LDH * 2 + 2 * 128 * LDW * 2)  // 169984

// ---------------- device scratch ----------------
__device__ __half g_W2[2][JT_ * 128 * H_];           // reordered whh fp16: [jt][g*32+h][k]
__device__ float  g_embp[2][(long)V_ * G4];          // emb @ wih^T + bih + bhh (exact fp32)
__device__ __half g_fcw16[V_ * H_];
__device__ float  g_biasfc[16 * V_];
__device__ __half g_hf[2][(long)B_ * H_];            // hidden fp16, double buffered (cross-CTA via L2)
__device__ __half g_hseq[(long)B_ * (T_ - 1) * H_];
__device__ float  g_logits[(long)B_ * (T_ - 1) * V_];
__device__ unsigned g_bar8[8 * 32];                  // per-b-group barrier counters (128B apart)

// fast activations: MUFU-based, rel err ~1e-6 (numerically validated R7-R9)
__device__ __forceinline__ float sigm(float x) {
    return __fdividef(1.f, 1.f + __expf(-x));
}
__device__ __forceinline__ float tanhfast(float x) {
    float s = __fdividef(1.f, 1.f + __expf(-2.f * x));
    return fmaf(2.f, s, -1.f);
}

__device__ __forceinline__ void cpa16(void* dst, const void* src) {
    unsigned d = (unsigned)__cvta_generic_to_shared(dst);
    asm volatile("cp.async.cg.shared.global [%0], [%1], 16;\n" :: "r"(d), "l"(src));
}
#define CPC()  asm volatile("cp.async.commit_group;\n" ::: "memory")
#define CPW(n) asm volatile("cp.async.wait_group %0;\n" :: "n"(n) : "memory")

// copy 64-k chunk ch of this CTA's h tile into smem buffer (all 512 threads)
#define CPCHUNK(buf, ch)                                                          \
    for (int i_ = threadIdx.x; i_ < 128 * 8; i_ += THREADS) {                     \
        int r_ = i_ >> 3, q_ = i_ & 7;                                            \
        cpa16((buf) + r_ * LDW + q_ * 8, hg + (long)(b0 + r_) * H_ + (ch) * 64 + q_ * 8); \
    }

// ---------------- prep A: embproj = emb @ wih^T + bih + bhh (exact fp32) ----------------
__global__ void prep_embproj(const float* __restrict__ emb, const float* __restrict__ wih,
                             const float* __restrict__ bih, const float* __restrict__ bhh,
                             int is_dec)
{
    __shared__ float er[E_];
    int v = blockIdx.x;
    int n = blockIdx.y * 256 + threadIdx.x;
    er[threadIdx.x] = emb[(long)v * E_ + threadIdx.x];
    __syncthreads();
    float s = bih[n] + bhh[n];
    const float* wr = wih + (long)n * E_;
    #pragma unroll 8
    for (int k = 0; k < E_; k++) s += er[k] * wr[k];
    g_embp[is_dec][(long)v * G4 + n] = s;
}

// ---------------- prep B: reorder whh fp16, fc weights, bias tile, zero h0, reset bars ---
__global__ void prep2(const float* __restrict__ enc_whh, const float* __restrict__ dec_whh,
                      const float* __restrict__ fc_w,    const float* __restrict__ fc_b)
{
    if (blockIdx.x == 0 && threadIdx.x < 8 * 32) g_bar8[threadIdx.x] = 0u;
    const long NW  = (long)JT_ * 128 * H_;
    const long NFC = (long)V_ * H_;
    const long NB  = 16L * V_;
    const long NS  = (long)B_ * H_;
    const long total = 2 * NW + NFC + NB + NS;
    for (long i = (long)blockIdx.x * blockDim.x + threadIdx.x; i < total;
         i += (long)gridDim.x * blockDim.x) {
        long r = i;
        if (r < 2 * NW) {
            int ed = (int)(r / NW);
            long l = r % NW;
            int jt = (int)(l / (128L * H_));
            int rr = (int)((l / H_) % 128);
            int k  = (int)(l % H_);
            int g = rr >> 5, hh = rr & 31;
            long n = (long)g * H_ + jt * 32 + hh;
            const float* whh = ed ? dec_whh : enc_whh;
            g_W2[ed][l] = __float2half(whh[n * H_ + k]);
        } else if (r < 2 * NW + NFC) {
            long l = r - 2 * NW;
            g_fcw16[l] = __float2half(fc_w[l]);
        } else if (r < 2 * NW + NFC + NB) {
            long l = r - 2 * NW - NFC;
            g_biasfc[l] = fc_b[l % V_];
        } else {
            long l = r - 2 * NW - NFC - NB;
            g_hf[0][l] = __float2half(0.f);
        }
    }
}

// ---------------- persistent kernel: all 255 LSTM steps ----------------
// CTA (bt, jt): batch rows bt*128..+127, h-dims jt*32..+31 (x4 gates = 128 gate rows).
// 16 warps: wk = warp>>3 splits K; (wj, wbt) tile 16j x 32b x 2cb. c state in wk=0 regs.
// Mainloop: ONE syncthreads per chunk iteration — the copy for pair c+2 is issued after
// the sync of iteration c+1, which already proves every warp finished reading the target
// buffer. Cross-CTA h via L2 (STG -> tid0 fence.gpu (cumulative) -> 16-CTA barrier).
__global__ __launch_bounds__(THREADS, 1) void seq_kernel(
    const int* __restrict__ src, const int* __restrict__ tgt)
{
    extern __shared__ __align__(16) char smem[];
    __half* Ws = (__half*)smem;                       // [128 gate-row][LDH k] resident
    __half* hb[4];
    #pragma unroll
    for (int i = 0; i < 4; i++) hb[i] = (__half*)(smem + WBYTES + i * CHUNKB);
    float* GS   = (float*)(smem + WBYTES);            // [128 b][132 j] gate staging (aliases hb)
    float* hout = (float*)(smem + WBYTES + GS_B);     // [128 b][36 h]
    __shared__ int tok_s[128];

    const int tid  = threadIdx.x;
    const int warp = tid >> 5;
    const int wk   = warp >> 3;         // K half
    const int wj   = warp & 1;          // j sub-tile (16)
    const int wbt  = (warp >> 1) & 3;   // batch sub-tile (32)
    const int jt   = blockIdx.x & 15;
    const int b0   = (blockIdx.x >> 4) * 128;
    const int btg  = blockIdx.x >> 4;   // barrier group

    // resident encoder W tile
    {
        const __half* __restrict__ W = g_W2[0] + (long)jt * 128 * H_;
        for (int i = tid; i < 128 * 64; i += THREADS) {
            int r = i >> 6, q = i & 63;
            cpa16(Ws + r * LDH + q * 8, W + (long)r * H_ + q * 8);
        }
        CPC(); CPW(0);
        __syncthreads();
    }

    // persistent cell state (wk=0 warps only)
    wmma::fragment<wmma::accumulator, 16, 16, 16, float> cfr[2];
    wmma::fill_fragment(cfr[0], 0.f);
    wmma::fill_fragment(cfr[1], 0.f);

    for (int st = 0; st < NSTEP; ++st) {
        const int is_dec = st >= S_;
        const int t   = is_dec ? st - S_ : st;
        const int par = st & 1;
        const int* __restrict__ tok = is_dec ? tgt : src;
        const __half* __restrict__ hg = g_hf[par];

        if (st == S_) {   // swap to decoder weights (CTA-local)
            const __half* __restrict__ W = g_W2[1] + (long)jt * 128 * H_;
            for (int i = tid; i < 128 * 64; i += THREADS) {
                int r = i >> 6, q = i & 63;
                cpa16(Ws + r * LDH + q * 8, W + (long)r * H_ + q * 8);
            }
            CPC(); CPW(0);
            __syncthreads();
        }

        if (tid < 128) tok_s[tid] = tok[(long)(b0 + tid) * 128 + t];

        // prologue: pair0 = chunks {0,4}, pair1 = {1,5}
        CPCHUNK(hb[0], 0); CPCHUNK(hb[2], 4); CPC();
        CPCHUNK(hb[1], 1); CPCHUNK(hb[3], 5); CPC();

        wmma::fragment<wmma::accumulator, 16, 16, 16, float> acc[4][2];
        #pragma unroll
        for (int g = 0; g < 4; g++) {
            wmma::fill_fragment(acc[g][0], 0.f);
            wmma::fill_fragment(acc[g][1], 0.f);
        }

        // single-sync pipelined mainloop (see header comment for the safety argument)
        #pragma unroll 1
        for (int c = 0; c < 4; c++) {
            if (c == 0) { CPW(1); } else { CPW(0); }
            __syncthreads();
            if (c == 1)      { CPCHUNK(hb[0], 2); CPCHUNK(hb[2], 6); CPC(); }
            else if (c == 2) { CPCHUNK(hb[1], 3); CPCHUNK(hb[3], 7); CPC(); }
            const __half* cw = hb[2 * wk + (c & 1)];
            const int ch = wk * 4 + c;           // this warp's K chunk
            #pragma unroll
            for (int kk = 0; kk < 4; kk++) {
                wmma::fragment<wmma::matrix_b, 16, 16, 16, half, wmma::col_major> bf[2];
                #pragma unroll
                for (int cb = 0; cb < 2; cb++)
                    wmma::load_matrix_sync(bf[cb], cw + (wbt * 32 + cb * 16) * LDW + kk * 16, LDW);
                #pragma unroll
                for (int g = 0; g < 4; g++) {
                    wmma::fragment<wmma::matrix_a, 16, 16, 16, half, wmma::row_major> af;
                    wmma::load_matrix_sync(af, Ws + (g * 32 + wj * 16) * LDH + ch * 64 + kk * 16, LDH);
                    wmma::mma_sync(acc[g][0], af, bf[0], acc[g][0]);
                    wmma::mma_sync(acc[g][1], af, bf[1], acc[g][1]);
                }
            }
        }
        __syncthreads();   // all warps done reading hb -> GS alias region free

        // -------- epilogue (R5 structure: wk=1 stores, wk=0 finalizes) --------
        if (wk == 1) {
            #pragma unroll
            for (int g = 0; g < 4; g++)
                #pragma unroll
                for (int cb = 0; cb < 2; cb++)
                    wmma::store_matrix_sync(GS + (wbt * 32 + cb * 16) * 132 + g * 32 + wj * 16,
                                            acc[g][cb], 132, wmma::mem_col_major);
        }
        __syncthreads();

        // all threads: GS += embproj gather (vectorized)
        const float* __restrict__ EP = g_embp[is_dec];
        for (int i = tid; i < 128 * 32; i += THREADS) {
            int b = i >> 5, j4 = (i & 31) * 4;
            int g = j4 >> 5, hh = j4 & 31;
            const float4 ev = *reinterpret_cast<const float4*>(
                &EP[(long)tok_s[b] * G4 + (long)g * H_ + jt * 32 + hh]);
            float4* gp = reinterpret_cast<float4*>(&GS[b * 132 + j4]);
            float4 gv = *gp;
            gv.x += ev.x; gv.y += ev.y; gv.z += ev.z; gv.w += ev.w;
            *gp = gv;
        }
        __syncthreads();

        // wk=0 warps: combine + cell update (c in registers), stage h
        if (wk == 0) {
            #pragma unroll
            for (int cb = 0; cb < 2; cb++) {
                const int bl = wbt * 32 + cb * 16;
                wmma::fragment<wmma::accumulator, 16, 16, 16, float> xf, hn;
                #pragma unroll
                for (int g = 0; g < 4; g++) {
                    wmma::load_matrix_sync(xf, GS + bl * 132 + g * 32 + wj * 16, 132, wmma::mem_col_major);
                    #pragma unroll
                    for (int e = 0; e < 8; e++) acc[g][cb].x[e] += xf.x[e];
                }
                #pragma unroll
                for (int e = 0; e < 8; e++) {
                    float ig = sigm(acc[0][cb].x[e]);
                    float fg = sigm(acc[1][cb].x[e]);
                    float gg = tanhfast(acc[2][cb].x[e]);
                    float og = sigm(acc[3][cb].x[e]);
                    float c2 = fg * cfr[cb].x[e] + ig * gg;
                    cfr[cb].x[e] = c2;
                    hn.x[e] = og * tanhfast(c2);
                }
                wmma::store_matrix_sync(hout + bl * 36 + wj * 16, hn, 36, wmma::mem_col_major);
            }
        }
        __syncthreads();

        // all threads: write h (fp16) to global, vectorized (4 halves per iteration)
        __half* __restrict__ hg2 = g_hf[par ^ 1];
        for (int i = tid; i < 128 * 8; i += THREADS) {
            int b = i >> 3, q = i & 7;
            float4 hv = *reinterpret_cast<const float4*>(&hout[b * 36 + q * 4]);
            __half2 h2a = __floats2half2_rn(hv.x, hv.y);
            __half2 h2b = __floats2half2_rn(hv.z, hv.w);
            uint2 o = make_uint2(*reinterpret_cast<uint32_t*>(&h2a),
                                 *reinterpret_cast<uint32_t*>(&h2b));
            *reinterpret_cast<uint2*>(&hg2[(long)(b0 + b) * H_ + jt * 32 + q * 4]) = o;
            if (is_dec)
                *reinterpret_cast<uint2*>(
                    &g_hseq[((long)(b0 + b) * (T_ - 1) + t) * H_ + jt * 32 + q * 4]) = o;
        }

        // -------- per-b-group barrier (16 CTAs), tid0-only cumulative fence --------
        if (st + 1 < NSTEP) {
            __syncthreads();
            if (tid == 0) {
                __threadfence();                   // cumulative after syncthreads
                atomicAdd(&g_bar8[btg * 32], 1u);
                const unsigned target = (unsigned)(st + 1) * 16u;
                while (*(volatile unsigned*)&g_bar8[btg * 32] < target) __nanosleep(64);
            }
            __syncthreads();
        }
    }
}

// ---------------- FC head: logits = h_seq @ fc_w^T + fc_b (fp16 in, fp32 acc) ----------
__global__ __launch_bounds__(256, 1) void fc_kernel()
{
    extern __shared__ __align__(16) char smem[];
    __half* bsm = (__half*)smem;
    __half* ab0 = (__half*)(smem + 128 * LDH * 2);
    __half* ab1 = (__half*)(smem + 128 * LDH * 2 + 128 * LDW * 2);

    const int tid = threadIdx.x;
    const int warp = tid >> 5;
    const int wm = warp >> 2;
    const int wn = warp & 3;
    const long m0 = (long)blockIdx.x * 128;

    for (int i = tid; i < 128 * 64; i += 256) {
        int r = i >> 6, q = i & 63;
        cpa16(bsm + r * LDH + q * 8, g_fcw16 + (long)r * H_ + q * 8);
    }
    for (int i = tid; i < 128 * 8; i += 256) {
        int r = i >> 3, q = i & 7;
        cpa16(ab0 + r * LDW + q * 8, g_hseq + (m0 + r) * H_ + q * 8);
    }
    CPC();
    for (int i = tid; i < 128 * 8; i += 256) {
        int r = i >> 3, q = i & 7;
        cpa16(ab1 + r * LDW + q * 8, g_hseq + (m0 + r) * H_ + 64 + q * 8);
    }
    CPC();
    CPW(1);
    __syncthreads();

    wmma::fragment<wmma::accumulator, 16, 16, 16, float> acc[4][2];
    #pragma unroll
    for (int mm = 0; mm < 4; mm++)
        #pragma unroll
        for (int cb = 0; cb < 2; cb++)
            wmma::load_matrix_sync(acc[mm][cb], g_biasfc + wn * 32 + cb * 16, V_, wmma::mem_row_major);

    #pragma unroll 1
    for (int ch = 0; ch < 8; ch++) {
        const __half* ca = (ch & 1) ? ab1 : ab0;
        #pragma unroll
        for (int kk = 0; kk < 4; kk++) {
            wmma::fragment<wmma::matrix_b, 16, 16, 16, half, wmma::col_major> bf[2];
            #pragma unroll
            for (int cb = 0; cb < 2; cb++)
                wmma::load_matrix_sync(bf[cb], bsm + (wn * 32 + cb * 16) * LDH + ch * 64 + kk * 16, LDH);
            #pragma unroll
            for (int mm = 0; mm < 4; mm++) {
                wmma::fragment<wmma::matrix_a, 16, 16, 16, half, wmma::row_major> af;
                wmma::load_matrix_sync(af, ca + (wm * 64 + mm * 16) * LDW + kk * 16, LDW);
                wmma::mma_sync(acc[mm][0], af, bf[0], acc[mm][0]);
                wmma::mma_sync(acc[mm][1], af, bf[1], acc[mm][1]);
            }
        }
        __syncthreads();
        if (ch + 2 < 8) {
            __half* nb = (ch & 1) ? ab1 : ab0;
            for (int i = tid; i < 128 * 8; i += 256) {
                int r = i >> 3, q = i & 7;
                cpa16(nb + r * LDW + q * 8, g_hseq + (m0 + r) * H_ + (ch + 2) * 64 + q * 8);
            }
            CPC();
        }
        if (ch + 1 < 8) {
            if (ch + 2 < 8) { CPW(1); } else { CPW(0); }
            __syncthreads();
        }
    }

    #pragma unroll
    for (int mm = 0; mm < 4; mm++)
        #pragma unroll
        for (int cb = 0; cb < 2; cb++)
            wmma::store_matrix_sync(g_logits + (m0 + wm * 64 + mm * 16) * V_ + wn * 32 + cb * 16,
                                    acc[mm][cb], V_, wmma::mem_row_major);
}

// ---------------- scatter logits into (B, T, V) with zero row at t=0 ----------------
__global__ void out_kernel(float* __restrict__ out)
{
    const long n4 = (long)B_ * T_ * V_ / 4;
    for (long i = (long)blockIdx.x * blockDim.x + threadIdx.x; i < n4;
         i += (long)gridDim.x * blockDim.x) {
        long e = i * 4;
        int  v  = (int)(e % V_);
        long bt = e / V_;
        int  tt = (int)(bt % T_);
        long b  = bt / T_;
        float4 val;
        if (tt == 0) val = make_float4(0.f, 0.f, 0.f, 0.f);
        else val = *reinterpret_cast<const float4*>(
                       &g_logits[(b * (T_ - 1) + (tt - 1)) * V_ + v]);
        reinterpret_cast<float4*>(out)[i] = val;
    }
}

// ---------------- launch ----------------
extern "C" void kernel_launch(void* const* d_in, const int* in_sizes, int n_in,
                              void* d_out, int out_size)
{
    (void)in_sizes; (void)n_in; (void)out_size;
    const int*   src      = (const int*)  d_in[0];
    const int*   target   = (const int*)  d_in[1];
    const float* emb      = (const float*)d_in[2];
    const float* dec_emb  = (const float*)d_in[3];
    const float* enc_wih  = (const float*)d_in[4];
    const float* enc_whh  = (const float*)d_in[5];
    const float* enc_bih  = (const float*)d_in[6];
    const float* enc_bhh  = (const float*)d_in[7];
    const float* dec_wih  = (const float*)d_in[8];
    const float* dec_whh  = (const float*)d_in[9];
    const float* dec_bih  = (const float*)d_in[10];
    const float* dec_bhh  = (const float*)d_in[11];
    const float* fc_w     = (const float*)d_in[12];
    const float* fc_b     = (const float*)d_in[13];
    float* out = (float*)d_out;

    cudaFuncSetAttribute(seq_kernel, cudaFuncAttributeMaxDynamicSharedMemorySize, SEQ_SMEM);
    cudaFuncSetAttribute(fc_kernel,  cudaFuncAttributeMaxDynamicSharedMemorySize, FC_SMEM);

    prep_embproj<<<dim3(V_, G4 / 256), 256>>>(emb,     enc_wih, enc_bih, enc_bhh, 0);
    prep_embproj<<<dim3(V_, G4 / 256), 256>>>(dec_emb, dec_wih, dec_bih, dec_bhh, 1);
    prep2<<<2048, 256>>>(enc_whh, dec_whh, fc_w, fc_b);

    seq_kernel<<<NCTA, THREADS, SEQ_SMEM>>>(src, target);

    fc_kernel<<<(B_ * (T_ - 1)) / 128, 256, FC_SMEM>>>();
    out_kernel<<<2048, 256>>>(out);
}

// round 13
// speedup vs baseline: 1.9826x; 1.0317x over previous
#include <cuda_runtime.h>
#include <cuda_fp16.h>
#include <mma.h>
#include <cstdint>

using namespace nvcuda;

#define B_   1024
#define H_   512
#define E_   256
#define S_   128
#define T_   128
#define V_   128
#define G4   2048
#define NCTA 256                 // 32 j-tiles x 8 b-groups
#define NSTEP (S_ + T_ - 1)      // 255
#define THREADS 256
#define LDH  520                 // smem ld (halves) for resident W rows
#define LDW  72                  // smem ld (halves) for streamed h chunks
#define CHUNKB (128 * LDW * 2)   // 18432 bytes per 64-k chunk
#define W2BYTES (64 * LDH * 2)   // 66560: resident W tile (64 gate-rows)
#define GS2_B  (128 * 68 * 4)    // 34816: gate staging fp32 [128 b][68 j]
#define HO2_B  (128 * 20 * 4)    // 10240: hout fp32 [128 b][20 h]
#define SEQ_SMEM (W2BYTES + GS2_B + HO2_B)            // 111616 -> 2 CTAs = 223232 <= 227KB
#define FC_SMEM  (128 * LDH * 2 + 2 * 128 * LDW * 2)  // 169984

// ---------------- device scratch ----------------
__device__ __half g_W2[2][32 * 64 * H_];             // reordered whh fp16: [jh][gate*16+r][k]
__device__ float  g_embp[2][(long)V_ * G4];          // emb @ wih^T + bih + bhh (exact fp32)
__device__ __half g_fcw16[V_ * H_];
__device__ float  g_biasfc[16 * V_];
__device__ __half g_hf[2][(long)B_ * H_];            // hidden fp16, double buffered (cross-CTA via L2)
__device__ __half g_hseq[(long)B_ * (T_ - 1) * H_];
__device__ float  g_logits[(long)B_ * (T_ - 1) * V_];
__device__ unsigned g_bar8[8 * 32];                  // per-b-group barrier counters (128B apart)

// fast activations: MUFU-based, rel err ~1e-6 (validated R7-R12)
__device__ __forceinline__ float sigm(float x) {
    return __fdividef(1.f, 1.f + __expf(-x));
}
__device__ __forceinline__ float tanhfast(float x) {
    float s = __fdividef(1.f, 1.f + __expf(-2.f * x));
    return fmaf(2.f, s, -1.f);
}

__device__ __forceinline__ void cpa16(void* dst, const void* src) {
    unsigned d = (unsigned)__cvta_generic_to_shared(dst);
    asm volatile("cp.async.cg.shared.global [%0], [%1], 16;\n" :: "r"(d), "l"(src));
}
#define CPC()  asm volatile("cp.async.commit_group;\n" ::: "memory")
#define CPW(n) asm volatile("cp.async.wait_group %0;\n" :: "n"(n) : "memory")

// copy 64-k chunk ch of this CTA's h tile into smem buffer (all 256 threads)
#define CPCH(buf, ch)                                                             \
    for (int i_ = threadIdx.x; i_ < 128 * 8; i_ += THREADS) {                     \
        int r_ = i_ >> 3, q_ = i_ & 7;                                            \
        cpa16((buf) + r_ * LDW + q_ * 8, hg + (long)(b0 + r_) * H_ + (ch) * 64 + q_ * 8); \
    }

// ---------------- prep A: embproj = emb @ wih^T + bih + bhh (exact fp32) ----------------
__global__ void prep_embproj(const float* __restrict__ emb, const float* __restrict__ wih,
                             const float* __restrict__ bih, const float* __restrict__ bhh,
                             int is_dec)
{
    __shared__ float er[E_];
    int v = blockIdx.x;
    int n = blockIdx.y * 256 + threadIdx.x;
    er[threadIdx.x] = emb[(long)v * E_ + threadIdx.x];
    __syncthreads();
    float s = bih[n] + bhh[n];
    const float* wr = wih + (long)n * E_;
    #pragma unroll 8
    for (int k = 0; k < E_; k++) s += er[k] * wr[k];
    g_embp[is_dec][(long)v * G4 + n] = s;
}

// ---------------- prep B: reorder whh fp16 (32 j-tiles of 16h x 4 gates), fc, h0, bars ---
__global__ void prep2(const float* __restrict__ enc_whh, const float* __restrict__ dec_whh,
                      const float* __restrict__ fc_w,    const float* __restrict__ fc_b)
{
    if (blockIdx.x == 0 && threadIdx.x < 8 * 32) g_bar8[threadIdx.x] = 0u;
    const long NW  = 32L * 64 * H_;
    const long NFC = (long)V_ * H_;
    const long NB  = 16L * V_;
    const long NS  = (long)B_ * H_;
    const long total = 2 * NW + NFC + NB + NS;
    for (long i = (long)blockIdx.x * blockDim.x + threadIdx.x; i < total;
         i += (long)gridDim.x * blockDim.x) {
        long r = i;
        if (r < 2 * NW) {
            int ed = (int)(r / NW);
            long l = r % NW;
            int jh = (int)(l / (64L * H_));
            int rr = (int)((l / H_) % 64);
            int k  = (int)(l % H_);
            int g = rr >> 4, hh = rr & 15;
            long n = (long)g * H_ + jh * 16 + hh;
            const float* whh = ed ? dec_whh : enc_whh;
            g_W2[ed][l] = __float2half(whh[n * H_ + k]);
        } else if (r < 2 * NW + NFC) {
            long l = r - 2 * NW;
            g_fcw16[l] = __float2half(fc_w[l]);
        } else if (r < 2 * NW + NFC + NB) {
            long l = r - 2 * NW - NFC;
            g_biasfc[l] = fc_b[l % V_];
        } else {
            long l = r - 2 * NW - NFC - NB;
            g_hf[0][l] = __float2half(0.f);
        }
    }
}

// ---------------- persistent kernel: all 255 LSTM steps, 2 CTAs per SM ----------------
// CTA (bg, jh): batch rows bg*128..+127, h-dims jh*16..+15 (x4 gates = 64 gate rows).
// 8 warps: wk = warp>>2 splits K (256 each); wb = warp&3 tiles batch (32 each, 2 cb).
// acc[4][2] per warp (identical shape to the proven R11 kernel). c state in wk=0 regs.
// Occupancy 2: co-resident CTA hides copy waits, syncs, and barrier skew.
__global__ __launch_bounds__(THREADS, 2) void seq_kernel(
    const int* __restrict__ src, const int* __restrict__ tgt)
{
    extern __shared__ __align__(16) char smem[];
    __half* Ws  = (__half*)smem;                        // [64 gate-row][LDH k] resident
    __half* hb0 = (__half*)(smem + W2BYTES);            // wk=0 chunk buffer
    __half* hb1 = (__half*)(smem + W2BYTES + CHUNKB);   // wk=1 chunk buffer
    float*  GS   = (float*)(smem + W2BYTES);            // [128 b][68 j] (aliases hb0/hb1)
    float*  hout = (float*)(smem + W2BYTES + GS2_B);    // [128 b][20 h]
    __shared__ int tok_s[128];

    const int tid  = threadIdx.x;
    const int warp = tid >> 5;
    const int wk   = warp >> 2;         // K half
    const int wb   = warp & 3;          // batch sub-tile (32)
    const int jh   = blockIdx.x & 31;
    const int b0   = (blockIdx.x >> 5) * 128;
    const int btg  = blockIdx.x >> 5;   // barrier group (32 CTAs each)

    // resident encoder W tile (64 rows x 512 k)
    {
        const __half* __restrict__ W = g_W2[0] + (long)jh * 64 * H_;
        for (int i = tid; i < 64 * 64; i += THREADS) {
            int r = i >> 6, q = i & 63;
            cpa16(Ws + r * LDH + q * 8, W + (long)r * H_ + q * 8);
        }
        CPC(); CPW(0);
        __syncthreads();
    }

    // persistent cell state (wk=0 warps only): 16 h x 32 b per warp
    wmma::fragment<wmma::accumulator, 16, 16, 16, float> cfr[2];
    wmma::fill_fragment(cfr[0], 0.f);
    wmma::fill_fragment(cfr[1], 0.f);

    for (int st = 0; st < NSTEP; ++st) {
        const int is_dec = st >= S_;
        const int t   = is_dec ? st - S_ : st;
        const int par = st & 1;
        const int* __restrict__ tok = is_dec ? tgt : src;
        const __half* __restrict__ hg = g_hf[par];

        if (st == S_) {   // swap to decoder weights (CTA-local)
            const __half* __restrict__ W = g_W2[1] + (long)jh * 64 * H_;
            for (int i = tid; i < 64 * 64; i += THREADS) {
                int r = i >> 6, q = i & 63;
                cpa16(Ws + r * LDH + q * 8, W + (long)r * H_ + q * 8);
            }
            CPC(); CPW(0);
            __syncthreads();
        }

        if (tid < 128) tok_s[tid] = tok[(long)(b0 + tid) * 128 + t];

        // prologue: chunk 0 (wk0) and 4 (wk1)
        CPCH(hb0, 0); CPCH(hb1, 4); CPC();

        wmma::fragment<wmma::accumulator, 16, 16, 16, float> acc[4][2];
        #pragma unroll
        for (int g = 0; g < 4; g++) {
            wmma::fill_fragment(acc[g][0], 0.f);
            wmma::fill_fragment(acc[g][1], 0.f);
        }

        #pragma unroll 1
        for (int c = 0; c < 4; c++) {
            CPW(0);
            __syncthreads();
            const __half* cw = wk ? hb1 : hb0;
            const int ch = wk * 4 + c;           // this warp's K chunk
            #pragma unroll
            for (int kk = 0; kk < 4; kk++) {
                wmma::fragment<wmma::matrix_b, 16, 16, 16, half, wmma::col_major> bf[2];
                #pragma unroll
                for (int cb = 0; cb < 2; cb++)
                    wmma::load_matrix_sync(bf[cb], cw + (wb * 32 + cb * 16) * LDW + kk * 16, LDW);
                #pragma unroll
                for (int g = 0; g < 4; g++) {
                    wmma::fragment<wmma::matrix_a, 16, 16, 16, half, wmma::row_major> af;
                    wmma::load_matrix_sync(af, Ws + (g * 16) * LDH + ch * 64 + kk * 16, LDH);
                    wmma::mma_sync(acc[g][0], af, bf[0], acc[g][0]);
                    wmma::mma_sync(acc[g][1], af, bf[1], acc[g][1]);
                }
            }
            __syncthreads();                     // all warps done reading buffers
            if (c < 3) {
                CPCH(hb0, c + 1);
                CPCH(hb1, c + 5);
                CPC();
            }
        }

        // -------- epilogue (asymmetric, spill-safe: wk=1 stores, wk=0 finalizes) --------
        if (wk == 1) {
            #pragma unroll
            for (int g = 0; g < 4; g++)
                #pragma unroll
                for (int cb = 0; cb < 2; cb++)
                    wmma::store_matrix_sync(GS + (wb * 32 + cb * 16) * 68 + g * 16,
                                            acc[g][cb], 68, wmma::mem_col_major);
        }
        __syncthreads();

        // all threads: GS += embproj gather (float4; 16 f4 per batch row)
        const float* __restrict__ EP = g_embp[is_dec];
        #pragma unroll
        for (int it = 0; it < 8; it++) {
            int i = tid + it * THREADS;          // 2048 total
            int b = i >> 4, f = i & 15;
            int g = f >> 2, q = f & 3;
            const float4 ev = *reinterpret_cast<const float4*>(
                &EP[(long)tok_s[b] * G4 + (long)g * H_ + jh * 16 + q * 4]);
            float* gp = &GS[b * 68 + g * 16 + q * 4];
            float4 gv = *reinterpret_cast<float4*>(gp);
            gv.x += ev.x; gv.y += ev.y; gv.z += ev.z; gv.w += ev.w;
            *reinterpret_cast<float4*>(gp) = gv;
        }
        __syncthreads();

        // wk=0 warps: combine + cell update (c in registers), stage h
        if (wk == 0) {
            #pragma unroll
            for (int cb = 0; cb < 2; cb++) {
                const int bl = wb * 32 + cb * 16;
                wmma::fragment<wmma::accumulator, 16, 16, 16, float> xf, hn;
                #pragma unroll
                for (int g = 0; g < 4; g++) {
                    wmma::load_matrix_sync(xf, GS + bl * 68 + g * 16, 68, wmma::mem_col_major);
                    #pragma unroll
                    for (int e = 0; e < 8; e++) acc[g][cb].x[e] += xf.x[e];
                }
                #pragma unroll
                for (int e = 0; e < 8; e++) {
                    float ig = sigm(acc[0][cb].x[e]);
                    float fg = sigm(acc[1][cb].x[e]);
                    float gg = tanhfast(acc[2][cb].x[e]);
                    float og = sigm(acc[3][cb].x[e]);
                    float c2 = fg * cfr[cb].x[e] + ig * gg;
                    cfr[cb].x[e] = c2;
                    hn.x[e] = og * tanhfast(c2);
                }
                wmma::store_matrix_sync(hout + bl * 20, hn, 20, wmma::mem_col_major);
            }
        }
        __syncthreads();

        // all threads: write h (fp16), vectorized (4 halves each, 2 per thread)
        __half* __restrict__ hg2 = g_hf[par ^ 1];
        #pragma unroll
        for (int it = 0; it < 2; it++) {
            int i = tid + it * THREADS;          // 512 total
            int b = i >> 2, q = i & 3;
            float4 hv = *reinterpret_cast<const float4*>(&hout[b * 20 + q * 4]);
            __half2 h2a = __floats2half2_rn(hv.x, hv.y);
            __half2 h2b = __floats2half2_rn(hv.z, hv.w);
            uint2 o = make_uint2(*reinterpret_cast<uint32_t*>(&h2a),
                                 *reinterpret_cast<uint32_t*>(&h2b));
            *reinterpret_cast<uint2*>(&hg2[(long)(b0 + b) * H_ + jh * 16 + q * 4]) = o;
            if (is_dec)
                *reinterpret_cast<uint2*>(
                    &g_hseq[((long)(b0 + b) * (T_ - 1) + t) * H_ + jh * 16 + q * 4]) = o;
        }

        // -------- per-b-group barrier (32 CTAs), tid0-only cumulative fence --------
        if (st + 1 < NSTEP) {
            __syncthreads();
            if (tid == 0) {
                __threadfence();                   // cumulative after syncthreads
                atomicAdd(&g_bar8[btg * 32], 1u);
                const unsigned target = (unsigned)(st + 1) * 32u;
                while (*(volatile unsigned*)&g_bar8[btg * 32] < target) __nanosleep(64);
            }
            __syncthreads();
        }
    }
}

// ---------------- FC head: logits = h_seq @ fc_w^T + fc_b (fp16 in, fp32 acc) ----------
__global__ __launch_bounds__(256, 1) void fc_kernel()
{
    extern __shared__ __align__(16) char smem[];
    __half* bsm = (__half*)smem;
    __half* ab0 = (__half*)(smem + 128 * LDH * 2);
    __half* ab1 = (__half*)(smem + 128 * LDH * 2 + 128 * LDW * 2);

    const int tid = threadIdx.x;
    const int warp = tid >> 5;
    const int wm = warp >> 2;
    const int wn = warp & 3;
    const long m0 = (long)blockIdx.x * 128;

    for (int i = tid; i < 128 * 64; i += 256) {
        int r = i >> 6, q = i & 63;
        cpa16(bsm + r * LDH + q * 8, g_fcw16 + (long)r * H_ + q * 8);
    }
    for (int i = tid; i < 128 * 8; i += 256) {
        int r = i >> 3, q = i & 7;
        cpa16(ab0 + r * LDW + q * 8, g_hseq + (m0 + r) * H_ + q * 8);
    }
    CPC();
    for (int i = tid; i < 128 * 8; i += 256) {
        int r = i >> 3, q = i & 7;
        cpa16(ab1 + r * LDW + q * 8, g_hseq + (m0 + r) * H_ + 64 + q * 8);
    }
    CPC();
    CPW(1);
    __syncthreads();

    wmma::fragment<wmma::accumulator, 16, 16, 16, float> acc[4][2];
    #pragma unroll
    for (int mm = 0; mm < 4; mm++)
        #pragma unroll
        for (int cb = 0; cb < 2; cb++)
            wmma::load_matrix_sync(acc[mm][cb], g_biasfc + wn * 32 + cb * 16, V_, wmma::mem_row_major);

    #pragma unroll 1
    for (int ch = 0; ch < 8; ch++) {
        const __half* ca = (ch & 1) ? ab1 : ab0;
        #pragma unroll
        for (int kk = 0; kk < 4; kk++) {
            wmma::fragment<wmma::matrix_b, 16, 16, 16, half, wmma::col_major> bf[2];
            #pragma unroll
            for (int cb = 0; cb < 2; cb++)
                wmma::load_matrix_sync(bf[cb], bsm + (wn * 32 + cb * 16) * LDH + ch * 64 + kk * 16, LDH);
            #pragma unroll
            for (int mm = 0; mm < 4; mm++) {
                wmma::fragment<wmma::matrix_a, 16, 16, 16, half, wmma::row_major> af;
                wmma::load_matrix_sync(af, ca + (wm * 64 + mm * 16) * LDW + kk * 16, LDW);
                wmma::mma_sync(acc[mm][0], af, bf[0], acc[mm][0]);
                wmma::mma_sync(acc[mm][1], af, bf[1], acc[mm][1]);
            }
        }
        __syncthreads();
        if (ch + 2 < 8) {
            __half* nb = (ch & 1) ? ab1 : ab0;
            for (int i = tid; i < 128 * 8; i += 256) {
                int r = i >> 3, q = i & 7;
                cpa16(nb + r * LDW + q * 8, g_hseq + (m0 + r) * H_ + (ch + 2) * 64 + q * 8);
            }
            CPC();
        }
        if (ch + 1 < 8) {
            if (ch + 2 < 8) { CPW(1); } else { CPW(0); }
            __syncthreads();
        }
    }

    #pragma unroll
    for (int mm = 0; mm < 4; mm++)
        #pragma unroll
        for (int cb = 0; cb < 2; cb++)
            wmma::store_matrix_sync(g_logits + (m0 + wm * 64 + mm * 16) * V_ + wn * 32 + cb * 16,
                                    acc[mm][cb], V_, wmma::mem_row_major);
}

// ---------------- scatter logits into (B, T, V) with zero row at t=0 ----------------
__global__ void out_kernel(float* __restrict__ out)
{
    const long n4 = (long)B_ * T_ * V_ / 4;
    for (long i = (long)blockIdx.x * blockDim.x + threadIdx.x; i < n4;
         i += (long)gridDim.x * blockDim.x) {
        long e = i * 4;
        int  v  = (int)(e % V_);
        long bt = e / V_;
        int  tt = (int)(bt % T_);
        long b  = bt / T_;
        float4 val;
        if (tt == 0) val = make_float4(0.f, 0.f, 0.f, 0.f);
        else val = *reinterpret_cast<const float4*>(
                       &g_logits[(b * (T_ - 1) + (tt - 1)) * V_ + v]);
        reinterpret_cast<float4*>(out)[i] = val;
    }
}

// ---------------- launch ----------------
extern "C" void kernel_launch(void* const* d_in, const int* in_sizes, int n_in,
                              void* d_out, int out_size)
{
    (void)in_sizes; (void)n_in; (void)out_size;
    const int*   src      = (const int*)  d_in[0];
    const int*   target   = (const int*)  d_in[1];
    const float* emb      = (const float*)d_in[2];
    const float* dec_emb  = (const float*)d_in[3];
    const float* enc_wih  = (const float*)d_in[4];
    const float* enc_whh  = (const float*)d_in[5];
    const float* enc_bih  = (const float*)d_in[6];
    const float* enc_bhh  = (const float*)d_in[7];
    const float* dec_wih  = (const float*)d_in[8];
    const float* dec_whh  = (const float*)d_in[9];
    const float* dec_bih  = (const float*)d_in[10];
    const float* dec_bhh  = (const float*)d_in[11];
    const float* fc_w     = (const float*)d_in[12];
    const float* fc_b     = (const float*)d_in[13];
    float* out = (float*)d_out;

    cudaFuncSetAttribute(seq_kernel, cudaFuncAttributeMaxDynamicSharedMemorySize, SEQ_SMEM);
    cudaFuncSetAttribute(fc_kernel,  cudaFuncAttributeMaxDynamicSharedMemorySize, FC_SMEM);

    prep_embproj<<<dim3(V_, G4 / 256), 256>>>(emb,     enc_wih, enc_bih, enc_bhh, 0);
    prep_embproj<<<dim3(V_, G4 / 256), 256>>>(dec_emb, dec_wih, dec_bih, dec_bhh, 1);
    prep2<<<2048, 256>>>(enc_whh, dec_whh, fc_w, fc_b);

    seq_kernel<<<NCTA, THREADS, SEQ_SMEM>>>(src, target);

    fc_kernel<<<(B_ * (T_ - 1)) / 128, 256, FC_SMEM>>>();
    out_kernel<<<2048, 256>>>(out);
}